// round 1
// baseline (speedup 1.0000x reference)
#include <cuda_runtime.h>

// Problem constants
#define BB   64
#define TT   512
#define NTOT 32768      // BB*TT
#define FF   1024
#define DD   128

// Scratch (device globals; no allocation allowed)
__device__ float g_G[DD * NTOT];   // fc1 output, layout [d][n]
__device__ float g_Y[DD * NTOT];   // lstm-projected output, layout [d][n]
__device__ float g_M[BB * DD];     // sum over t of lrelu(e1)

__device__ __forceinline__ float sigf(float x) {
    return 1.f / (1.f + __expf(-x));
}
__device__ __forceinline__ float tanh_fast(float x) {
    // tanh(x) = 2*sigmoid(2x) - 1
    return 2.f / (1.f + __expf(-2.f * x)) - 1.f;
}

// ----------------------------------------------------------------------------
// Kernel 1: fc1 GEMM.  G[d][b*TT+t] = sum_f fc1_w[d][f] * x[b][f][t] + fc1_b[d]
// Per-batch GEMM: C(128 x 512) = W(128 x 1024) @ Xb(1024 x 512).
// Block tile 128(d) x 128(t), K-chunks of 8, 256 threads, 8x8 per thread.
// ----------------------------------------------------------------------------
__global__ __launch_bounds__(256) void fc1_kernel(const float* __restrict__ x,
                                                  const float* __restrict__ w,
                                                  const float* __restrict__ bias)
{
    __shared__ float As[8][128];   // As[k][d]
    __shared__ float Bs[8][128];   // Bs[k][t]

    const int tid = threadIdx.x;
    const int bt  = blockIdx.y;          // batch
    const int t0  = blockIdx.x * 128;    // t tile
    const float* xb = x + (size_t)bt * FF * TT;

    float acc[8][8];
#pragma unroll
    for (int i = 0; i < 8; i++)
#pragma unroll
        for (int j = 0; j < 8; j++) acc[i][j] = 0.f;

    const int dl = tid >> 1;             // 0..127 (W load row)
    const int kl = (tid & 1) * 4;        // 0 or 4
    const int ky = tid >> 5;             // 0..7  (X load k)
    const int ty = (tid & 31) * 4;       // 0..124

    const int df = (tid >> 4) * 8;       // d fragment base
    const int tf = (tid & 15) * 8;       // t fragment base

    for (int f0 = 0; f0 < FF; f0 += 8) {
        float4 wv = *reinterpret_cast<const float4*>(w + dl * FF + f0 + kl);
        float4 xv = *reinterpret_cast<const float4*>(xb + (size_t)(f0 + ky) * TT + t0 + ty);
        __syncthreads();
        As[kl + 0][dl] = wv.x;
        As[kl + 1][dl] = wv.y;
        As[kl + 2][dl] = wv.z;
        As[kl + 3][dl] = wv.w;
        *reinterpret_cast<float4*>(&Bs[ky][ty]) = xv;
        __syncthreads();
#pragma unroll
        for (int k = 0; k < 8; k++) {
            float a[8], b[8];
#pragma unroll
            for (int i = 0; i < 8; i++) a[i] = As[k][df + i];
#pragma unroll
            for (int j = 0; j < 8; j++) b[j] = Bs[k][tf + j];
#pragma unroll
            for (int i = 0; i < 8; i++)
#pragma unroll
                for (int j = 0; j < 8; j++) acc[i][j] = fmaf(a[i], b[j], acc[i][j]);
        }
    }

    const int nbase = bt * TT + t0;
#pragma unroll
    for (int i = 0; i < 8; i++) {
        const float bv = bias[df + i];
        float* gp = g_G + (size_t)(df + i) * NTOT + nbase + tf;
#pragma unroll
        for (int j = 0; j < 8; j++) gp[j] = acc[i][j] + bv;
    }
}

// ----------------------------------------------------------------------------
// Kernel 2: bidirectional LSTM over the d axis (H=1), fused with lout.
// One thread per sequence n. Coalesced across n for every d step.
// Y[d][n] = lw0*fwd_h[d] + lw1*bwd_h[d] + lb
// ----------------------------------------------------------------------------
__global__ __launch_bounds__(256) void lstm_kernel(
    const float* __restrict__ wih_f, const float* __restrict__ whh_f,
    const float* __restrict__ bih_f, const float* __restrict__ bhh_f,
    const float* __restrict__ wih_b, const float* __restrict__ whh_b,
    const float* __restrict__ bih_b, const float* __restrict__ bhh_b,
    const float* __restrict__ lout_w, const float* __restrict__ lout_b)
{
    const int n = blockIdx.x * blockDim.x + threadIdx.x;
    const float lw0 = lout_w[0], lw1 = lout_w[1], lb = lout_b[0];

    float wi[4], wh[4], bs[4];
#pragma unroll
    for (int k = 0; k < 4; k++) { wi[k] = wih_f[k]; wh[k] = whh_f[k]; bs[k] = bih_f[k] + bhh_f[k]; }

    // forward scan d = 0..127
    float h = 0.f, c = 0.f;
    for (int d = 0; d < DD; d++) {
        const float xv = g_G[(size_t)d * NTOT + n];
        const float ig = sigf(fmaf(wi[0], xv, fmaf(wh[0], h, bs[0])));
        const float fg = sigf(fmaf(wi[1], xv, fmaf(wh[1], h, bs[1])));
        const float gg = tanh_fast(fmaf(wi[2], xv, fmaf(wh[2], h, bs[2])));
        const float og = sigf(fmaf(wi[3], xv, fmaf(wh[3], h, bs[3])));
        c = fmaf(fg, c, ig * gg);
        h = og * tanh_fast(c);
        g_Y[(size_t)d * NTOT + n] = fmaf(lw0, h, lb);
    }

#pragma unroll
    for (int k = 0; k < 4; k++) { wi[k] = wih_b[k]; wh[k] = whh_b[k]; bs[k] = bih_b[k] + bhh_b[k]; }

    // backward scan d = 127..0
    h = 0.f; c = 0.f;
    for (int d = DD - 1; d >= 0; d--) {
        const float xv = g_G[(size_t)d * NTOT + n];
        const float ig = sigf(fmaf(wi[0], xv, fmaf(wh[0], h, bs[0])));
        const float fg = sigf(fmaf(wi[1], xv, fmaf(wh[1], h, bs[1])));
        const float gg = tanh_fast(fmaf(wi[2], xv, fmaf(wh[2], h, bs[2])));
        const float og = sigf(fmaf(wi[3], xv, fmaf(wh[3], h, bs[3])));
        c = fmaf(fg, c, ig * gg);
        h = og * tanh_fast(c);
        g_Y[(size_t)d * NTOT + n] = fmaf(lw1, h, g_Y[(size_t)d * NTOT + n]);
    }
}

// ----------------------------------------------------------------------------
// Kernel 3a: zero the mean accumulator.
// ----------------------------------------------------------------------------
__global__ void zero_kernel()
{
    const int i = blockIdx.x * blockDim.x + threadIdx.x;
    if (i < BB * DD) g_M[i] = 0.f;
}

// ----------------------------------------------------------------------------
// Kernel 3b: e1 = Y^T @ emb_w1^T + b1, lrelu, sum over t into g_M[b][j].
// Block tile: 128(n) x 128(j), K = d = 128 in chunks of 8.
// The mean over t commutes past the (linear) second embedding layer, so we
// only accumulate the per-batch sum of lrelu(e1) here.
// ----------------------------------------------------------------------------
__global__ __launch_bounds__(256) void emb1_kernel(const float* __restrict__ w1,
                                                   const float* __restrict__ b1)
{
    __shared__ float Ys[8][128];     // Ys[k][n]
    __shared__ float Ws[8][128];     // Ws[k][j]
    __shared__ float red[16][128];   // per-n-group partial sums over n

    const int tid = threadIdx.x;
    const int n0  = blockIdx.x * 128;

    float acc[8][8];
#pragma unroll
    for (int i = 0; i < 8; i++)
#pragma unroll
        for (int j = 0; j < 8; j++) acc[i][j] = 0.f;

    const int jl = tid >> 1;            // w1 load row (j)
    const int kl = (tid & 1) * 4;
    const int ky = tid >> 5;            // Y load k
    const int ny = (tid & 31) * 4;

    const int nf = (tid >> 4) * 8;      // n fragment base
    const int jf = (tid & 15) * 8;      // j fragment base

    for (int d0 = 0; d0 < DD; d0 += 8) {
        float4 wv = *reinterpret_cast<const float4*>(w1 + jl * DD + d0 + kl);
        float4 yv = *reinterpret_cast<const float4*>(g_Y + (size_t)(d0 + ky) * NTOT + n0 + ny);
        __syncthreads();
        Ws[kl + 0][jl] = wv.x;
        Ws[kl + 1][jl] = wv.y;
        Ws[kl + 2][jl] = wv.z;
        Ws[kl + 3][jl] = wv.w;
        *reinterpret_cast<float4*>(&Ys[ky][ny]) = yv;
        __syncthreads();
#pragma unroll
        for (int k = 0; k < 8; k++) {
            float a[8], b[8];
#pragma unroll
            for (int i = 0; i < 8; i++) a[i] = Ys[k][nf + i];
#pragma unroll
            for (int j = 0; j < 8; j++) b[j] = Ws[k][jf + j];
#pragma unroll
            for (int i = 0; i < 8; i++)
#pragma unroll
                for (int j = 0; j < 8; j++) acc[i][j] = fmaf(a[i], b[j], acc[i][j]);
        }
    }

    // epilogue: bias + leaky relu + sum over this thread's 8 n-rows
    float psum[8];
#pragma unroll
    for (int j = 0; j < 8; j++) psum[j] = 0.f;
#pragma unroll
    for (int j = 0; j < 8; j++) {
        const float bv = b1[jf + j];
#pragma unroll
        for (int i = 0; i < 8; i++) {
            float e = acc[i][j] + bv;
            e = (e >= 0.f) ? e : 0.2f * e;
            psum[j] += e;
        }
    }
    __syncthreads();
#pragma unroll
    for (int j = 0; j < 8; j++) red[tid >> 4][jf + j] = psum[j];
    __syncthreads();

    if (tid < 128) {
        float s = 0.f;
#pragma unroll
        for (int g = 0; g < 16; g++) s += red[g][tid];
        const int b = n0 / TT;
        atomicAdd(&g_M[b * DD + tid], s);
    }
}

// ----------------------------------------------------------------------------
// Kernel 4: out[b][i] = (1/T) * sum_j g_M[b][j] * emb_w2[i][j] + emb_b2[i]
// ----------------------------------------------------------------------------
__global__ __launch_bounds__(128) void out_kernel(const float* __restrict__ w2,
                                                  const float* __restrict__ b2,
                                                  float* __restrict__ out)
{
    __shared__ float m[128];
    const int b = blockIdx.x;
    const int i = threadIdx.x;
    m[i] = g_M[b * DD + i] * (1.f / (float)TT);
    __syncthreads();
    float s = b2[i];
    const float* wr = w2 + i * DD;
#pragma unroll 16
    for (int j = 0; j < DD; j++) s = fmaf(m[j], wr[j], s);
    out[b * DD + i] = s;
}

// ----------------------------------------------------------------------------
extern "C" void kernel_launch(void* const* d_in, const int* in_sizes, int n_in,
                              void* d_out, int out_size)
{
    const float* x      = (const float*)d_in[0];
    const float* fc1_w  = (const float*)d_in[1];
    const float* fc1_b  = (const float*)d_in[2];
    const float* wih_f  = (const float*)d_in[3];
    const float* whh_f  = (const float*)d_in[4];
    const float* bih_f  = (const float*)d_in[5];
    const float* bhh_f  = (const float*)d_in[6];
    const float* wih_b  = (const float*)d_in[7];
    const float* whh_b  = (const float*)d_in[8];
    const float* bih_b  = (const float*)d_in[9];
    const float* bhh_b  = (const float*)d_in[10];
    const float* lout_w = (const float*)d_in[11];
    const float* lout_b = (const float*)d_in[12];
    const float* emb_w1 = (const float*)d_in[13];
    const float* emb_b1 = (const float*)d_in[14];
    const float* emb_w2 = (const float*)d_in[15];
    const float* emb_b2 = (const float*)d_in[16];
    float* out = (float*)d_out;

    fc1_kernel<<<dim3(TT / 128, BB), 256>>>(x, fc1_w, fc1_b);
    lstm_kernel<<<NTOT / 256, 256>>>(wih_f, whh_f, bih_f, bhh_f,
                                     wih_b, whh_b, bih_b, bhh_b,
                                     lout_w, lout_b);
    zero_kernel<<<(BB * DD + 255) / 256, 256>>>();
    emb1_kernel<<<NTOT / 128, 256>>>(emb_w1, emb_b1);
    out_kernel<<<BB, 128>>>(emb_w2, emb_b2, out);
}

// round 2
// speedup vs baseline: 1.7515x; 1.7515x over previous
#include <cuda_runtime.h>

// Problem constants
#define BB   64
#define TT   512
#define NTOT 32768      // BB*TT
#define FF   1024
#define DD   128

// Scratch (device globals; no allocation allowed)
__device__ float g_G[DD * NTOT];   // fc1 output, layout [d][n]
__device__ float g_Y[DD * NTOT];   // lstm-projected output, layout [d][n]
__device__ float g_M[BB * DD];     // sum over t of lrelu(e1)

__device__ __forceinline__ float sigf(float x) {
    return 1.f / (1.f + __expf(-x));
}
__device__ __forceinline__ float tanh_fast(float x) {
    return 2.f / (1.f + __expf(-2.f * x)) - 1.f;
}
__device__ __forceinline__ unsigned f2tf(float f) {
    unsigned r;
    asm("cvt.rna.tf32.f32 %0, %1;" : "=r"(r) : "f"(f));
    return r;
}
__device__ __forceinline__ void mma_tf32(float c[4], const unsigned a[4], const unsigned b[2]) {
    asm volatile(
        "mma.sync.aligned.m16n8k8.row.col.f32.tf32.tf32.f32 "
        "{%0,%1,%2,%3}, {%4,%5,%6,%7}, {%8,%9}, {%0,%1,%2,%3};"
        : "+f"(c[0]), "+f"(c[1]), "+f"(c[2]), "+f"(c[3])
        : "r"(a[0]), "r"(a[1]), "r"(a[2]), "r"(a[3]), "r"(b[0]), "r"(b[1]));
}

// ----------------------------------------------------------------------------
// Kernel 1: fc1 GEMM on tensor cores (tf32 mma.sync).
// G[d][b*TT+t] = sum_f fc1_w[d][f] * x[b][f][t] + fc1_b[d]
// CTA tile 128(d=M) x 128(t=N), K chunks of 16, double-buffered smem.
// 8 warps: warp_m = wid&1 (64 rows), warp_n = wid>>1 (32 cols).
// ----------------------------------------------------------------------------
#define PAD 136   // padded row stride (floats): frag loads conflict-free

__global__ __launch_bounds__(256) void fc1_mma_kernel(const float* __restrict__ x,
                                                      const float* __restrict__ w,
                                                      const float* __restrict__ bias)
{
    __shared__ unsigned As[2][16][PAD];   // tf32 bits, [k][m]
    __shared__ unsigned Bs[2][16][PAD];   // tf32 bits, [k][n]

    const int tid  = threadIdx.x;
    const int lane = tid & 31;
    const int wid  = tid >> 5;
    const int g    = lane >> 2;          // groupID 0..7
    const int tig  = lane & 3;           // thread-in-group 0..3

    const int wm = (wid & 1) * 64;       // warp m base
    const int wn = (wid >> 1) * 32;      // warp n base

    const int bt = blockIdx.y;           // batch
    const int t0 = blockIdx.x * 128;     // t tile
    const float* xb = x + (size_t)bt * FF * TT;

    // global load assignments
    const int dl = tid >> 1;             // w row (d), 0..127
    const int ka = (tid & 1) * 8;        // w k offset: 0 or 8 (two float4 each)
    const int fl = tid >> 4;             // x row (k), 0..15
    const int tq = (tid & 15) * 4;       // x t offset (two chunks: +0, +64)

    float4 w0, w1, x0, x1;

    // prefetch stage 0
    {
        const float* wp = w + (size_t)dl * FF + ka;
        w0 = *reinterpret_cast<const float4*>(wp);
        w1 = *reinterpret_cast<const float4*>(wp + 4);
        const float* xp = xb + (size_t)fl * TT + t0 + tq;
        x0 = *reinterpret_cast<const float4*>(xp);
        x1 = *reinterpret_cast<const float4*>(xp + 64);
    }

    float c[4][4][4];
#pragma unroll
    for (int i = 0; i < 4; i++)
#pragma unroll
        for (int j = 0; j < 4; j++)
#pragma unroll
            for (int k = 0; k < 4; k++) c[i][j][k] = 0.f;

    int buf = 0;
    for (int s = 0; s < FF / 16; s++) {
        // store prefetched stage into smem (with fp32 -> tf32 RNA conversion)
        As[buf][ka + 0][dl] = f2tf(w0.x);
        As[buf][ka + 1][dl] = f2tf(w0.y);
        As[buf][ka + 2][dl] = f2tf(w0.z);
        As[buf][ka + 3][dl] = f2tf(w0.w);
        As[buf][ka + 4][dl] = f2tf(w1.x);
        As[buf][ka + 5][dl] = f2tf(w1.y);
        As[buf][ka + 6][dl] = f2tf(w1.z);
        As[buf][ka + 7][dl] = f2tf(w1.w);
        Bs[buf][fl][tq + 0] = f2tf(x0.x);
        Bs[buf][fl][tq + 1] = f2tf(x0.y);
        Bs[buf][fl][tq + 2] = f2tf(x0.z);
        Bs[buf][fl][tq + 3] = f2tf(x0.w);
        Bs[buf][fl][tq + 64] = f2tf(x1.x);
        Bs[buf][fl][tq + 65] = f2tf(x1.y);
        Bs[buf][fl][tq + 66] = f2tf(x1.z);
        Bs[buf][fl][tq + 67] = f2tf(x1.w);
        __syncthreads();

        // prefetch next stage
        if (s + 1 < FF / 16) {
            const int f0 = (s + 1) * 16;
            const float* wp = w + (size_t)dl * FF + f0 + ka;
            w0 = *reinterpret_cast<const float4*>(wp);
            w1 = *reinterpret_cast<const float4*>(wp + 4);
            const float* xp = xb + (size_t)(f0 + fl) * TT + t0 + tq;
            x0 = *reinterpret_cast<const float4*>(xp);
            x1 = *reinterpret_cast<const float4*>(xp + 64);
        }

        // compute both k8 halves of this stage
#pragma unroll
        for (int kh = 0; kh < 16; kh += 8) {
            unsigned a[4][4], b[4][2];
#pragma unroll
            for (int mt = 0; mt < 4; mt++) {
                const int m = wm + mt * 16;
                a[mt][0] = As[buf][kh + tig][m + g];
                a[mt][1] = As[buf][kh + tig][m + g + 8];
                a[mt][2] = As[buf][kh + tig + 4][m + g];
                a[mt][3] = As[buf][kh + tig + 4][m + g + 8];
            }
#pragma unroll
            for (int nt = 0; nt < 4; nt++) {
                const int n = wn + nt * 8;
                b[nt][0] = Bs[buf][kh + tig][n + g];
                b[nt][1] = Bs[buf][kh + tig + 4][n + g];
            }
#pragma unroll
            for (int mt = 0; mt < 4; mt++)
#pragma unroll
                for (int nt = 0; nt < 4; nt++)
                    mma_tf32(c[mt][nt], a[mt], b[nt]);
        }
        buf ^= 1;
    }

    // epilogue: add bias, store to g_G[d][n]
    const int nbase = bt * TT + t0 + wn;
#pragma unroll
    for (int mt = 0; mt < 4; mt++) {
        const int dr = wm + mt * 16 + g;
        const float bv0 = bias[dr];
        const float bv1 = bias[dr + 8];
#pragma unroll
        for (int nt = 0; nt < 4; nt++) {
            const int ncol = nbase + nt * 8 + 2 * tig;
            float2 v0 = make_float2(c[mt][nt][0] + bv0, c[mt][nt][1] + bv0);
            float2 v1 = make_float2(c[mt][nt][2] + bv1, c[mt][nt][3] + bv1);
            *reinterpret_cast<float2*>(g_G + (size_t)dr * NTOT + ncol) = v0;
            *reinterpret_cast<float2*>(g_G + (size_t)(dr + 8) * NTOT + ncol) = v1;
        }
    }
}

// ----------------------------------------------------------------------------
// Kernel 2: bidirectional LSTM over the d axis (H=1), fused with lout.
// ----------------------------------------------------------------------------
__global__ __launch_bounds__(256) void lstm_kernel(
    const float* __restrict__ wih_f, const float* __restrict__ whh_f,
    const float* __restrict__ bih_f, const float* __restrict__ bhh_f,
    const float* __restrict__ wih_b, const float* __restrict__ whh_b,
    const float* __restrict__ bih_b, const float* __restrict__ bhh_b,
    const float* __restrict__ lout_w, const float* __restrict__ lout_b)
{
    const int n = blockIdx.x * blockDim.x + threadIdx.x;
    const float lw0 = lout_w[0], lw1 = lout_w[1], lb = lout_b[0];

    float wi[4], wh[4], bs[4];
#pragma unroll
    for (int k = 0; k < 4; k++) { wi[k] = wih_f[k]; wh[k] = whh_f[k]; bs[k] = bih_f[k] + bhh_f[k]; }

    float h = 0.f, c = 0.f;
    for (int d = 0; d < DD; d++) {
        const float xv = g_G[(size_t)d * NTOT + n];
        const float ig = sigf(fmaf(wi[0], xv, fmaf(wh[0], h, bs[0])));
        const float fg = sigf(fmaf(wi[1], xv, fmaf(wh[1], h, bs[1])));
        const float gg = tanh_fast(fmaf(wi[2], xv, fmaf(wh[2], h, bs[2])));
        const float og = sigf(fmaf(wi[3], xv, fmaf(wh[3], h, bs[3])));
        c = fmaf(fg, c, ig * gg);
        h = og * tanh_fast(c);
        g_Y[(size_t)d * NTOT + n] = fmaf(lw0, h, lb);
    }

#pragma unroll
    for (int k = 0; k < 4; k++) { wi[k] = wih_b[k]; wh[k] = whh_b[k]; bs[k] = bih_b[k] + bhh_b[k]; }

    h = 0.f; c = 0.f;
    for (int d = DD - 1; d >= 0; d--) {
        const float xv = g_G[(size_t)d * NTOT + n];
        const float ig = sigf(fmaf(wi[0], xv, fmaf(wh[0], h, bs[0])));
        const float fg = sigf(fmaf(wi[1], xv, fmaf(wh[1], h, bs[1])));
        const float gg = tanh_fast(fmaf(wi[2], xv, fmaf(wh[2], h, bs[2])));
        const float og = sigf(fmaf(wi[3], xv, fmaf(wh[3], h, bs[3])));
        c = fmaf(fg, c, ig * gg);
        h = og * tanh_fast(c);
        g_Y[(size_t)d * NTOT + n] = fmaf(lw1, h, g_Y[(size_t)d * NTOT + n]);
    }
}

// ----------------------------------------------------------------------------
// Kernel 3a: zero the mean accumulator.
// ----------------------------------------------------------------------------
__global__ void zero_kernel()
{
    const int i = blockIdx.x * blockDim.x + threadIdx.x;
    if (i < BB * DD) g_M[i] = 0.f;
}

// ----------------------------------------------------------------------------
// Kernel 3b: e1 = Y^T @ emb_w1^T + b1, lrelu, sum over t into g_M[b][j].
// ----------------------------------------------------------------------------
__global__ __launch_bounds__(256) void emb1_kernel(const float* __restrict__ w1,
                                                   const float* __restrict__ b1)
{
    __shared__ float Ys[8][128];
    __shared__ float Ws[8][128];
    __shared__ float red[16][128];

    const int tid = threadIdx.x;
    const int n0  = blockIdx.x * 128;

    float acc[8][8];
#pragma unroll
    for (int i = 0; i < 8; i++)
#pragma unroll
        for (int j = 0; j < 8; j++) acc[i][j] = 0.f;

    const int jl = tid >> 1;
    const int kl = (tid & 1) * 4;
    const int ky = tid >> 5;
    const int ny = (tid & 31) * 4;

    const int nf = (tid >> 4) * 8;
    const int jf = (tid & 15) * 8;

    for (int d0 = 0; d0 < DD; d0 += 8) {
        float4 wv = *reinterpret_cast<const float4*>(w1 + jl * DD + d0 + kl);
        float4 yv = *reinterpret_cast<const float4*>(g_Y + (size_t)(d0 + ky) * NTOT + n0 + ny);
        __syncthreads();
        Ws[kl + 0][jl] = wv.x;
        Ws[kl + 1][jl] = wv.y;
        Ws[kl + 2][jl] = wv.z;
        Ws[kl + 3][jl] = wv.w;
        *reinterpret_cast<float4*>(&Ys[ky][ny]) = yv;
        __syncthreads();
#pragma unroll
        for (int k = 0; k < 8; k++) {
            float a[8], b[8];
#pragma unroll
            for (int i = 0; i < 8; i++) a[i] = Ys[k][nf + i];
#pragma unroll
            for (int j = 0; j < 8; j++) b[j] = Ws[k][jf + j];
#pragma unroll
            for (int i = 0; i < 8; i++)
#pragma unroll
                for (int j = 0; j < 8; j++) acc[i][j] = fmaf(a[i], b[j], acc[i][j]);
        }
    }

    float psum[8];
#pragma unroll
    for (int j = 0; j < 8; j++) psum[j] = 0.f;
#pragma unroll
    for (int j = 0; j < 8; j++) {
        const float bv = b1[jf + j];
#pragma unroll
        for (int i = 0; i < 8; i++) {
            float e = acc[i][j] + bv;
            e = (e >= 0.f) ? e : 0.2f * e;
            psum[j] += e;
        }
    }
    __syncthreads();
#pragma unroll
    for (int j = 0; j < 8; j++) red[tid >> 4][jf + j] = psum[j];
    __syncthreads();

    if (tid < 128) {
        float s = 0.f;
#pragma unroll
        for (int g = 0; g < 16; g++) s += red[g][tid];
        const int b = n0 / TT;
        atomicAdd(&g_M[b * DD + tid], s);
    }
}

// ----------------------------------------------------------------------------
// Kernel 4: out[b][i] = (1/T) * sum_j g_M[b][j] * emb_w2[i][j] + emb_b2[i]
// ----------------------------------------------------------------------------
__global__ __launch_bounds__(128) void out_kernel(const float* __restrict__ w2,
                                                  const float* __restrict__ b2,
                                                  float* __restrict__ out)
{
    __shared__ float m[128];
    const int b = blockIdx.x;
    const int i = threadIdx.x;
    m[i] = g_M[b * DD + i] * (1.f / (float)TT);
    __syncthreads();
    float s = b2[i];
    const float* wr = w2 + i * DD;
#pragma unroll 16
    for (int j = 0; j < DD; j++) s = fmaf(m[j], wr[j], s);
    out[b * DD + i] = s;
}

// ----------------------------------------------------------------------------
extern "C" void kernel_launch(void* const* d_in, const int* in_sizes, int n_in,
                              void* d_out, int out_size)
{
    const float* x      = (const float*)d_in[0];
    const float* fc1_w  = (const float*)d_in[1];
    const float* fc1_b  = (const float*)d_in[2];
    const float* wih_f  = (const float*)d_in[3];
    const float* whh_f  = (const float*)d_in[4];
    const float* bih_f  = (const float*)d_in[5];
    const float* bhh_f  = (const float*)d_in[6];
    const float* wih_b  = (const float*)d_in[7];
    const float* whh_b  = (const float*)d_in[8];
    const float* bih_b  = (const float*)d_in[9];
    const float* bhh_b  = (const float*)d_in[10];
    const float* lout_w = (const float*)d_in[11];
    const float* lout_b = (const float*)d_in[12];
    const float* emb_w1 = (const float*)d_in[13];
    const float* emb_b1 = (const float*)d_in[14];
    const float* emb_w2 = (const float*)d_in[15];
    const float* emb_b2 = (const float*)d_in[16];
    float* out = (float*)d_out;

    fc1_mma_kernel<<<dim3(TT / 128, BB), 256>>>(x, fc1_w, fc1_b);
    lstm_kernel<<<NTOT / 256, 256>>>(wih_f, whh_f, bih_f, bhh_f,
                                     wih_b, whh_b, bih_b, bhh_b,
                                     lout_w, lout_b);
    zero_kernel<<<(BB * DD + 255) / 256, 256>>>();
    emb1_kernel<<<NTOT / 128, 256>>>(emb_w1, emb_b1);
    out_kernel<<<BB, 128>>>(emb_w2, emb_b2, out);
}

// round 3
// speedup vs baseline: 2.7290x; 1.5581x over previous
#include <cuda_runtime.h>
#include <cstdint>

// Problem constants
#define BB   64
#define TT   512
#define NTOT 32768      // BB*TT
#define FF   1024
#define DD   128

// Scratch (device globals; no allocation allowed)
__device__ float g_G[DD * NTOT];   // fc1 output, layout [d][n]
__device__ float g_Y[DD * NTOT];   // lstm-projected output, layout [d][n]
__device__ float g_M[BB * DD];     // sum over t of lrelu(e1)

// ---------------------------------------------------------------- helpers
__device__ __forceinline__ float mtanh(float x) {
    float y;
    asm("tanh.approx.f32 %0, %1;" : "=f"(y) : "f"(x));
    return y;
}
__device__ __forceinline__ unsigned sptr(const void* p) {
    return (unsigned)__cvta_generic_to_shared(p);
}
__device__ __forceinline__ void cp16(unsigned dst, const float* src) {
    asm volatile("cp.async.cg.shared.global [%0], [%1], 16;" :: "r"(dst), "l"(src));
}
#define CP_COMMIT() asm volatile("cp.async.commit_group;")
#define CP_WAIT1()  asm volatile("cp.async.wait_group 1;")

__device__ __forceinline__ void mma_tf32(float c[4], const unsigned a[4], const unsigned b[2]) {
    asm volatile(
        "mma.sync.aligned.m16n8k8.row.col.f32.tf32.tf32.f32 "
        "{%0,%1,%2,%3}, {%4,%5,%6,%7}, {%8,%9}, {%0,%1,%2,%3};"
        : "+f"(c[0]), "+f"(c[1]), "+f"(c[2]), "+f"(c[3])
        : "r"(a[0]), "r"(a[1]), "r"(a[2]), "r"(a[3]), "r"(b[0]), "r"(b[1]));
}

#define ASTR 20    // A smem row stride (floats): conflict-free frag loads
#define BSTR 136   // B smem row stride (floats): conflict-free frag loads

// ----------------------------------------------------------------------------
// Kernel 1: fc1 GEMM on tensor cores, cp.async double-buffered, BK=16.
// G[d][b*TT+t] = sum_f fc1_w[d][f] * x[b][f][t] + fc1_b[d]
// CTA tile 128(d=M) x 128(t=N). Raw fp32 bits fed to tf32 MMA (HW truncates).
// ----------------------------------------------------------------------------
__global__ __launch_bounds__(256) void fc1_mma_kernel(const float* __restrict__ x,
                                                      const float* __restrict__ w,
                                                      const float* __restrict__ bias)
{
    __shared__ __align__(16) float As[2][128 * ASTR];   // [m][k]
    __shared__ __align__(16) float Bs[2][16 * BSTR];    // [k][n]

    const int tid  = threadIdx.x;
    const int lane = tid & 31;
    const int wid  = tid >> 5;
    const int g    = lane >> 2;
    const int tig  = lane & 3;
    const int wm   = (wid & 1) * 64;
    const int wn   = (wid >> 1) * 32;

    const int bt = blockIdx.y;
    const int t0 = blockIdx.x * 128;
    const float* xb = x + (size_t)bt * FF * TT;

    const int rowA = tid >> 1;            // d row for A loads
    const int kA   = (tid & 1) * 8;       // k offset (floats)
    const int rowB = tid >> 4;            // k row for B loads
    const int nB   = (tid & 15) * 8;      // t offset (floats)

    const unsigned dA0 = sptr(&As[0][rowA * ASTR + kA]);
    const unsigned dA1 = sptr(&As[1][rowA * ASTR + kA]);
    const unsigned dB0 = sptr(&Bs[0][rowB * BSTR + nB]);
    const unsigned dB1 = sptr(&Bs[1][rowB * BSTR + nB]);

    float c[4][4][4];
#pragma unroll
    for (int i = 0; i < 4; i++)
#pragma unroll
        for (int j = 0; j < 4; j++)
#pragma unroll
            for (int k = 0; k < 4; k++) c[i][j][k] = 0.f;

    // prologue: stage 0
    {
        const float* wp = w + (size_t)rowA * FF + kA;
        cp16(dA0, wp); cp16(dA0 + 16, wp + 4);
        const float* xp = xb + (size_t)rowB * TT + t0 + nB;
        cp16(dB0, xp); cp16(dB0 + 16, xp + 4);
        CP_COMMIT();
    }

    for (int s = 0; s < FF / 16; s++) {
        // issue stage s+1
        if (s + 1 < FF / 16) {
            const int f0 = (s + 1) * 16;
            const unsigned da = (s & 1) ? dA0 : dA1;
            const unsigned db = (s & 1) ? dB0 : dB1;
            const float* wp = w + (size_t)rowA * FF + f0 + kA;
            cp16(da, wp); cp16(da + 16, wp + 4);
            const float* xp = xb + (size_t)(f0 + rowB) * TT + t0 + nB;
            cp16(db, xp); cp16(db + 16, xp + 4);
        }
        CP_COMMIT();
        CP_WAIT1();              // stage s landed
        __syncthreads();

        const float* A = As[s & 1];
        const float* B = Bs[s & 1];
#pragma unroll
        for (int kh = 0; kh < 16; kh += 8) {
            unsigned a[4][4], b[4][2];
#pragma unroll
            for (int mt = 0; mt < 4; mt++) {
                const int m = wm + mt * 16 + g;
                a[mt][0] = __float_as_uint(A[m * ASTR + kh + tig]);
                a[mt][1] = __float_as_uint(A[(m + 8) * ASTR + kh + tig]);
                a[mt][2] = __float_as_uint(A[m * ASTR + kh + tig + 4]);
                a[mt][3] = __float_as_uint(A[(m + 8) * ASTR + kh + tig + 4]);
            }
#pragma unroll
            for (int nt = 0; nt < 4; nt++) {
                const int n = wn + nt * 8 + g;
                b[nt][0] = __float_as_uint(B[(kh + tig) * BSTR + n]);
                b[nt][1] = __float_as_uint(B[(kh + tig + 4) * BSTR + n]);
            }
#pragma unroll
            for (int mt = 0; mt < 4; mt++)
#pragma unroll
                for (int nt = 0; nt < 4; nt++)
                    mma_tf32(c[mt][nt], a[mt], b[nt]);
        }
        __syncthreads();         // guard buffer reuse
    }

    // epilogue: add bias, store to g_G[d][n]
    const int nbase = bt * TT + t0 + wn;
#pragma unroll
    for (int mt = 0; mt < 4; mt++) {
        const int dr = wm + mt * 16 + g;
        const float bv0 = bias[dr];
        const float bv1 = bias[dr + 8];
#pragma unroll
        for (int nt = 0; nt < 4; nt++) {
            const int ncol = nbase + nt * 8 + 2 * tig;
            float2 v0 = make_float2(c[mt][nt][0] + bv0, c[mt][nt][1] + bv0);
            float2 v1 = make_float2(c[mt][nt][2] + bv1, c[mt][nt][3] + bv1);
            *reinterpret_cast<float2*>(g_G + (size_t)dr * NTOT + ncol) = v0;
            *reinterpret_cast<float2*>(g_G + (size_t)(dr + 8) * NTOT + ncol) = v1;
        }
    }
}

// ----------------------------------------------------------------------------
// Kernel 2: bidirectional LSTM over the d axis (H=1), fused with lout.
// MUFU.TANH path: sigmoid(x) = 0.5*tanh(x/2)+0.5 with pre-halved weights.
// ----------------------------------------------------------------------------
__global__ __launch_bounds__(256) void lstm_kernel(
    const float* __restrict__ wih_f, const float* __restrict__ whh_f,
    const float* __restrict__ bih_f, const float* __restrict__ bhh_f,
    const float* __restrict__ wih_b, const float* __restrict__ whh_b,
    const float* __restrict__ bih_b, const float* __restrict__ bhh_b,
    const float* __restrict__ lout_w, const float* __restrict__ lout_b)
{
    const int n = blockIdx.x * blockDim.x + threadIdx.x;
    const float lw0 = lout_w[0], lw1 = lout_w[1], lb = lout_b[0];

    // forward direction params (i,f,o halved; g full)
    float wi0 = 0.5f * wih_f[0], wh0 = 0.5f * whh_f[0], b0 = 0.5f * (bih_f[0] + bhh_f[0]);
    float wi1 = 0.5f * wih_f[1], wh1 = 0.5f * whh_f[1], b1 = 0.5f * (bih_f[1] + bhh_f[1]);
    float wi2 =        wih_f[2], wh2 =        whh_f[2], b2 =        (bih_f[2] + bhh_f[2]);
    float wi3 = 0.5f * wih_f[3], wh3 = 0.5f * whh_f[3], b3 = 0.5f * (bih_f[3] + bhh_f[3]);

    float h = 0.f, c = 0.f;
#pragma unroll 4
    for (int d = 0; d < DD; d++) {
        const float xv = g_G[(size_t)d * NTOT + n];
        const float si = fmaf(0.5f, mtanh(fmaf(wi0, xv, fmaf(wh0, h, b0))), 0.5f);
        const float sf = fmaf(0.5f, mtanh(fmaf(wi1, xv, fmaf(wh1, h, b1))), 0.5f);
        const float tg = mtanh(fmaf(wi2, xv, fmaf(wh2, h, b2)));
        const float so = fmaf(0.5f, mtanh(fmaf(wi3, xv, fmaf(wh3, h, b3))), 0.5f);
        c = fmaf(sf, c, si * tg);
        h = so * mtanh(c);
        g_Y[(size_t)d * NTOT + n] = fmaf(lw0, h, lb);
    }

    wi0 = 0.5f * wih_b[0]; wh0 = 0.5f * whh_b[0]; b0 = 0.5f * (bih_b[0] + bhh_b[0]);
    wi1 = 0.5f * wih_b[1]; wh1 = 0.5f * whh_b[1]; b1 = 0.5f * (bih_b[1] + bhh_b[1]);
    wi2 =        wih_b[2]; wh2 =        whh_b[2]; b2 =        (bih_b[2] + bhh_b[2]);
    wi3 = 0.5f * wih_b[3]; wh3 = 0.5f * whh_b[3]; b3 = 0.5f * (bih_b[3] + bhh_b[3]);

    h = 0.f; c = 0.f;
#pragma unroll 4
    for (int d = DD - 1; d >= 0; d--) {
        const float xv = g_G[(size_t)d * NTOT + n];
        const float si = fmaf(0.5f, mtanh(fmaf(wi0, xv, fmaf(wh0, h, b0))), 0.5f);
        const float sf = fmaf(0.5f, mtanh(fmaf(wi1, xv, fmaf(wh1, h, b1))), 0.5f);
        const float tg = mtanh(fmaf(wi2, xv, fmaf(wh2, h, b2)));
        const float so = fmaf(0.5f, mtanh(fmaf(wi3, xv, fmaf(wh3, h, b3))), 0.5f);
        c = fmaf(sf, c, si * tg);
        h = so * mtanh(c);
        g_Y[(size_t)d * NTOT + n] = fmaf(lw1, h, g_Y[(size_t)d * NTOT + n]);
    }
}

// ----------------------------------------------------------------------------
// Kernel 3a: zero the mean accumulator.
// ----------------------------------------------------------------------------
__global__ void zero_kernel()
{
    const int i = blockIdx.x * blockDim.x + threadIdx.x;
    if (i < BB * DD) g_M[i] = 0.f;
}

// ----------------------------------------------------------------------------
// Kernel 3b: e1 = Y^T @ emb_w1^T + b1, lrelu, sum over t -> atomicAdd g_M.
// Same tf32-MMA structure, K = 128 (8 stages of 16).
// ----------------------------------------------------------------------------
__global__ __launch_bounds__(256) void emb1_mma_kernel(const float* __restrict__ w1,
                                                       const float* __restrict__ b1v)
{
    __shared__ __align__(16) float As[2][128 * ASTR];   // [j][k]
    __shared__ __align__(16) float Bs[2][16 * BSTR];    // [k][n]

    const int tid  = threadIdx.x;
    const int lane = tid & 31;
    const int wid  = tid >> 5;
    const int g    = lane >> 2;
    const int tig  = lane & 3;
    const int wm   = (wid & 1) * 64;
    const int wn   = (wid >> 1) * 32;

    const int n0 = blockIdx.x * 128;

    const int rowA = tid >> 1;
    const int kA   = (tid & 1) * 8;
    const int rowB = tid >> 4;
    const int nB   = (tid & 15) * 8;

    const unsigned dA0 = sptr(&As[0][rowA * ASTR + kA]);
    const unsigned dA1 = sptr(&As[1][rowA * ASTR + kA]);
    const unsigned dB0 = sptr(&Bs[0][rowB * BSTR + nB]);
    const unsigned dB1 = sptr(&Bs[1][rowB * BSTR + nB]);

    float c[4][4][4];
#pragma unroll
    for (int i = 0; i < 4; i++)
#pragma unroll
        for (int j = 0; j < 4; j++)
#pragma unroll
            for (int k = 0; k < 4; k++) c[i][j][k] = 0.f;

    {
        const float* wp = w1 + (size_t)rowA * DD + kA;
        cp16(dA0, wp); cp16(dA0 + 16, wp + 4);
        const float* yp = g_Y + (size_t)rowB * NTOT + n0 + nB;
        cp16(dB0, yp); cp16(dB0 + 16, yp + 4);
        CP_COMMIT();
    }

    for (int s = 0; s < DD / 16; s++) {
        if (s + 1 < DD / 16) {
            const int d0 = (s + 1) * 16;
            const unsigned da = (s & 1) ? dA0 : dA1;
            const unsigned db = (s & 1) ? dB0 : dB1;
            const float* wp = w1 + (size_t)rowA * DD + d0 + kA;
            cp16(da, wp); cp16(da + 16, wp + 4);
            const float* yp = g_Y + (size_t)(d0 + rowB) * NTOT + n0 + nB;
            cp16(db, yp); cp16(db + 16, yp + 4);
        }
        CP_COMMIT();
        CP_WAIT1();
        __syncthreads();

        const float* A = As[s & 1];
        const float* B = Bs[s & 1];
#pragma unroll
        for (int kh = 0; kh < 16; kh += 8) {
            unsigned a[4][4], b[4][2];
#pragma unroll
            for (int mt = 0; mt < 4; mt++) {
                const int m = wm + mt * 16 + g;
                a[mt][0] = __float_as_uint(A[m * ASTR + kh + tig]);
                a[mt][1] = __float_as_uint(A[(m + 8) * ASTR + kh + tig]);
                a[mt][2] = __float_as_uint(A[m * ASTR + kh + tig + 4]);
                a[mt][3] = __float_as_uint(A[(m + 8) * ASTR + kh + tig + 4]);
            }
#pragma unroll
            for (int nt = 0; nt < 4; nt++) {
                const int n = wn + nt * 8 + g;
                b[nt][0] = __float_as_uint(B[(kh + tig) * BSTR + n]);
                b[nt][1] = __float_as_uint(B[(kh + tig + 4) * BSTR + n]);
            }
#pragma unroll
            for (int mt = 0; mt < 4; mt++)
#pragma unroll
                for (int nt = 0; nt < 4; nt++)
                    mma_tf32(c[mt][nt], a[mt], b[nt]);
        }
        __syncthreads();
    }

    // epilogue: bias + leaky-relu + sum over n, quad-reduce, atomicAdd
    const int bb = blockIdx.x >> 2;   // 128-wide n tiles, TT=512 -> 4 per batch
#pragma unroll
    for (int mt = 0; mt < 4; mt++) {
        const int jr = wm + mt * 16 + g;
        const float bv0 = b1v[jr];
        const float bv1 = b1v[jr + 8];
        float r0 = 0.f, r1 = 0.f;
#pragma unroll
        for (int nt = 0; nt < 4; nt++) {
            float e;
            e = c[mt][nt][0] + bv0; r0 += (e >= 0.f) ? e : 0.2f * e;
            e = c[mt][nt][1] + bv0; r0 += (e >= 0.f) ? e : 0.2f * e;
            e = c[mt][nt][2] + bv1; r1 += (e >= 0.f) ? e : 0.2f * e;
            e = c[mt][nt][3] + bv1; r1 += (e >= 0.f) ? e : 0.2f * e;
        }
        r0 += __shfl_xor_sync(0xffffffffu, r0, 1);
        r0 += __shfl_xor_sync(0xffffffffu, r0, 2);
        r1 += __shfl_xor_sync(0xffffffffu, r1, 1);
        r1 += __shfl_xor_sync(0xffffffffu, r1, 2);
        if (tig == 0) {
            atomicAdd(&g_M[bb * DD + jr], r0);
            atomicAdd(&g_M[bb * DD + jr + 8], r1);
        }
    }
}

// ----------------------------------------------------------------------------
// Kernel 4: out[b][i] = (1/T) * sum_j g_M[b][j] * emb_w2[i][j] + emb_b2[i]
// ----------------------------------------------------------------------------
__global__ __launch_bounds__(128) void out_kernel(const float* __restrict__ w2,
                                                  const float* __restrict__ b2,
                                                  float* __restrict__ out)
{
    __shared__ float m[128];
    const int b = blockIdx.x;
    const int i = threadIdx.x;
    m[i] = g_M[b * DD + i] * (1.f / (float)TT);
    __syncthreads();
    float s = b2[i];
    const float* wr = w2 + i * DD;
#pragma unroll 16
    for (int j = 0; j < DD; j++) s = fmaf(m[j], wr[j], s);
    out[b * DD + i] = s;
}

// ----------------------------------------------------------------------------
extern "C" void kernel_launch(void* const* d_in, const int* in_sizes, int n_in,
                              void* d_out, int out_size)
{
    const float* x      = (const float*)d_in[0];
    const float* fc1_w  = (const float*)d_in[1];
    const float* fc1_b  = (const float*)d_in[2];
    const float* wih_f  = (const float*)d_in[3];
    const float* whh_f  = (const float*)d_in[4];
    const float* bih_f  = (const float*)d_in[5];
    const float* bhh_f  = (const float*)d_in[6];
    const float* wih_b  = (const float*)d_in[7];
    const float* whh_b  = (const float*)d_in[8];
    const float* bih_b  = (const float*)d_in[9];
    const float* bhh_b  = (const float*)d_in[10];
    const float* lout_w = (const float*)d_in[11];
    const float* lout_b = (const float*)d_in[12];
    const float* emb_w1 = (const float*)d_in[13];
    const float* emb_b1 = (const float*)d_in[14];
    const float* emb_w2 = (const float*)d_in[15];
    const float* emb_b2 = (const float*)d_in[16];
    float* out = (float*)d_out;

    fc1_mma_kernel<<<dim3(TT / 128, BB), 256>>>(x, fc1_w, fc1_b);
    lstm_kernel<<<NTOT / 256, 256>>>(wih_f, whh_f, bih_f, bhh_f,
                                     wih_b, whh_b, bih_b, bhh_b,
                                     lout_w, lout_b);
    zero_kernel<<<(BB * DD + 255) / 256, 256>>>();
    emb1_mma_kernel<<<NTOT / 128, 256>>>(emb_w1, emb_b1);
    out_kernel<<<BB, 128>>>(emb_w2, emb_b2, out);
}

// round 4
// speedup vs baseline: 2.8204x; 1.0335x over previous
#include <cuda_runtime.h>
#include <cstdint>

// Problem constants
#define BB   64
#define TT   512
#define NTOT 32768      // BB*TT
#define FF   1024
#define DD   128

// Scratch (device globals; no allocation allowed)
__device__ float g_G[DD * NTOT];       // fc1 output, layout [d][n]
__device__ float g_Y[2 * DD * NTOT];   // rows 0..127: lw0*h_fwd+lb ; rows 128..255: lw1*h_bwd
__device__ float g_M[BB * DD];         // sum over t of lrelu(e1)

// ---------------------------------------------------------------- helpers
__device__ __forceinline__ float mtanh(float x) {
    float y;
    asm("tanh.approx.f32 %0, %1;" : "=f"(y) : "f"(x));
    return y;
}
__device__ __forceinline__ unsigned sptr(const void* p) {
    return (unsigned)__cvta_generic_to_shared(p);
}
__device__ __forceinline__ void cp16(unsigned dst, const float* src) {
    asm volatile("cp.async.cg.shared.global [%0], [%1], 16;" :: "r"(dst), "l"(src));
}
#define CP_COMMIT() asm volatile("cp.async.commit_group;")
#define CP_WAIT2()  asm volatile("cp.async.wait_group 2;")

__device__ __forceinline__ void mma_tf32(float c[4], const unsigned a[4], const unsigned b[2]) {
    asm volatile(
        "mma.sync.aligned.m16n8k8.row.col.f32.tf32.tf32.f32 "
        "{%0,%1,%2,%3}, {%4,%5,%6,%7}, {%8,%9}, {%0,%1,%2,%3};"
        : "+f"(c[0]), "+f"(c[1]), "+f"(c[2]), "+f"(c[3])
        : "r"(a[0]), "r"(a[1]), "r"(a[2]), "r"(a[3]), "r"(b[0]), "r"(b[1]));
}

#define ASTR 20            // A smem row stride (floats)
#define BSTR 136           // B smem row stride (floats)
#define STG_FLOATS (128 * ASTR + 16 * BSTR)   // 4736 floats per pipeline stage
#define BOFF (128 * ASTR)                      // B offset within a stage
#define SMEM_BYTES (4 * STG_FLOATS * 4)        // 75776 bytes

// ----------------------------------------------------------------------------
// Kernel 1: fc1 GEMM on tensor cores, 4-stage cp.async ring, BK=16.
// G[d][b*TT+t] = sum_f fc1_w[d][f] * x[b][f][t] + fc1_b[d]
// ----------------------------------------------------------------------------
__global__ __launch_bounds__(256) void fc1_mma_kernel(const float* __restrict__ x,
                                                      const float* __restrict__ w,
                                                      const float* __restrict__ bias)
{
    extern __shared__ __align__(16) float sm[];

    const int tid  = threadIdx.x;
    const int lane = tid & 31;
    const int wid  = tid >> 5;
    const int g    = lane >> 2;
    const int tig  = lane & 3;
    const int wm   = (wid & 1) * 64;
    const int wn   = (wid >> 1) * 32;

    const int bt = blockIdx.y;
    const int t0 = blockIdx.x * 128;
    const float* xb = x + (size_t)bt * FF * TT;

    const int rowA = tid >> 1;            // d row for A loads (0..127)
    const int kA   = (tid & 1) * 8;       // k offset (floats)
    const int rowB = tid >> 4;            // k row for B loads (0..15)
    const int nB   = (tid & 15) * 8;      // t offset (floats)

    unsigned aAddr[4], bAddr[4];
#pragma unroll
    for (int st = 0; st < 4; st++) {
        aAddr[st] = sptr(sm + st * STG_FLOATS + rowA * ASTR + kA);
        bAddr[st] = sptr(sm + st * STG_FLOATS + BOFF + rowB * BSTR + nB);
    }

    float c[4][4][4];
#pragma unroll
    for (int i = 0; i < 4; i++)
#pragma unroll
        for (int j = 0; j < 4; j++)
#pragma unroll
            for (int k = 0; k < 4; k++) c[i][j][k] = 0.f;

    // prologue: stages 0..2
#pragma unroll
    for (int s = 0; s < 3; s++) {
        const float* wp = w + (size_t)rowA * FF + s * 16 + kA;
        cp16(aAddr[s], wp); cp16(aAddr[s] + 16, wp + 4);
        const float* xp = xb + (size_t)(s * 16 + rowB) * TT + t0 + nB;
        cp16(bAddr[s], xp); cp16(bAddr[s] + 16, xp + 4);
        CP_COMMIT();
    }

    const int NS = FF / 16;   // 64 stages
    for (int s = 0; s < NS; s++) {
        CP_WAIT2();           // stage s landed (s+1, s+2 still pending)
        __syncthreads();      // all threads done with buffer (s+3)&3, data visible

        if (s + 3 < NS) {
            const int f0 = (s + 3) * 16;
            const int b3 = (s + 3) & 3;
            const float* wp = w + (size_t)rowA * FF + f0 + kA;
            cp16(aAddr[b3], wp); cp16(aAddr[b3] + 16, wp + 4);
            const float* xp = xb + (size_t)(f0 + rowB) * TT + t0 + nB;
            cp16(bAddr[b3], xp); cp16(bAddr[b3] + 16, xp + 4);
        }
        CP_COMMIT();

        const float* A = sm + (s & 3) * STG_FLOATS;
        const float* B = A + BOFF;
#pragma unroll
        for (int kh = 0; kh < 16; kh += 8) {
            unsigned a[4][4], b[4][2];
#pragma unroll
            for (int mt = 0; mt < 4; mt++) {
                const int m = wm + mt * 16 + g;
                a[mt][0] = __float_as_uint(A[m * ASTR + kh + tig]);
                a[mt][1] = __float_as_uint(A[(m + 8) * ASTR + kh + tig]);
                a[mt][2] = __float_as_uint(A[m * ASTR + kh + tig + 4]);
                a[mt][3] = __float_as_uint(A[(m + 8) * ASTR + kh + tig + 4]);
            }
#pragma unroll
            for (int nt = 0; nt < 4; nt++) {
                const int n = wn + nt * 8 + g;
                b[nt][0] = __float_as_uint(B[(kh + tig) * BSTR + n]);
                b[nt][1] = __float_as_uint(B[(kh + tig + 4) * BSTR + n]);
            }
#pragma unroll
            for (int mt = 0; mt < 4; mt++)
#pragma unroll
                for (int nt = 0; nt < 4; nt++)
                    mma_tf32(c[mt][nt], a[mt], b[nt]);
        }
    }

    // epilogue: add bias, store to g_G[d][n]
    const int nbase = bt * TT + t0 + wn;
#pragma unroll
    for (int mt = 0; mt < 4; mt++) {
        const int dr = wm + mt * 16 + g;
        const float bv0 = bias[dr];
        const float bv1 = bias[dr + 8];
#pragma unroll
        for (int nt = 0; nt < 4; nt++) {
            const int ncol = nbase + nt * 8 + 2 * tig;
            float2 v0 = make_float2(c[mt][nt][0] + bv0, c[mt][nt][1] + bv0);
            float2 v1 = make_float2(c[mt][nt][2] + bv1, c[mt][nt][3] + bv1);
            *reinterpret_cast<float2*>(g_G + (size_t)dr * NTOT + ncol) = v0;
            *reinterpret_cast<float2*>(g_G + (size_t)(dr + 8) * NTOT + ncol) = v1;
        }
    }
}

// ----------------------------------------------------------------------------
// Kernel 2: LSTM, one direction per blockIdx.y. H=1, MUFU.TANH path.
// dir 0 (fwd):  writes g_Y[d]       = lw0*h + lb
// dir 1 (bwd):  writes g_Y[128 + d] = lw1*h
// emb1 sums the two halves by linearity (K = 256).
// ----------------------------------------------------------------------------
__global__ __launch_bounds__(256) void lstm_kernel(
    const float* __restrict__ wih_f, const float* __restrict__ whh_f,
    const float* __restrict__ bih_f, const float* __restrict__ bhh_f,
    const float* __restrict__ wih_b, const float* __restrict__ whh_b,
    const float* __restrict__ bih_b, const float* __restrict__ bhh_b,
    const float* __restrict__ lout_w, const float* __restrict__ lout_b)
{
    const int n = blockIdx.x * blockDim.x + threadIdx.x;
    const int dir = blockIdx.y;

    const float* wih = dir ? wih_b : wih_f;
    const float* whh = dir ? whh_b : whh_f;
    const float* bih = dir ? bih_b : bih_f;
    const float* bhh = dir ? bhh_b : bhh_f;

    const float wi0 = 0.5f * wih[0], wh0 = 0.5f * whh[0], b0 = 0.5f * (bih[0] + bhh[0]);
    const float wi1 = 0.5f * wih[1], wh1 = 0.5f * whh[1], b1 = 0.5f * (bih[1] + bhh[1]);
    const float wi2 =        wih[2], wh2 =        whh[2], b2 =        (bih[2] + bhh[2]);
    const float wi3 = 0.5f * wih[3], wh3 = 0.5f * whh[3], b3 = 0.5f * (bih[3] + bhh[3]);

    const float lw = dir ? lout_w[1] : lout_w[0];
    const float lb = dir ? 0.f : lout_b[0];

    float h = 0.f, c = 0.f;
    if (dir == 0) {
#pragma unroll 4
        for (int d = 0; d < DD; d++) {
            const float xv = g_G[(size_t)d * NTOT + n];
            const float si = fmaf(0.5f, mtanh(fmaf(wi0, xv, fmaf(wh0, h, b0))), 0.5f);
            const float sf = fmaf(0.5f, mtanh(fmaf(wi1, xv, fmaf(wh1, h, b1))), 0.5f);
            const float tg = mtanh(fmaf(wi2, xv, fmaf(wh2, h, b2)));
            const float so = fmaf(0.5f, mtanh(fmaf(wi3, xv, fmaf(wh3, h, b3))), 0.5f);
            c = fmaf(sf, c, si * tg);
            h = so * mtanh(c);
            g_Y[(size_t)d * NTOT + n] = fmaf(lw, h, lb);
        }
    } else {
#pragma unroll 4
        for (int d = DD - 1; d >= 0; d--) {
            const float xv = g_G[(size_t)d * NTOT + n];
            const float si = fmaf(0.5f, mtanh(fmaf(wi0, xv, fmaf(wh0, h, b0))), 0.5f);
            const float sf = fmaf(0.5f, mtanh(fmaf(wi1, xv, fmaf(wh1, h, b1))), 0.5f);
            const float tg = mtanh(fmaf(wi2, xv, fmaf(wh2, h, b2)));
            const float so = fmaf(0.5f, mtanh(fmaf(wi3, xv, fmaf(wh3, h, b3))), 0.5f);
            c = fmaf(sf, c, si * tg);
            h = so * mtanh(c);
            g_Y[(size_t)(DD + d) * NTOT + n] = lw * h;
        }
    }
}

// ----------------------------------------------------------------------------
// Kernel 3a: zero the mean accumulator.
// ----------------------------------------------------------------------------
__global__ void zero_kernel()
{
    const int i = blockIdx.x * blockDim.x + threadIdx.x;
    if (i < BB * DD) g_M[i] = 0.f;
}

// ----------------------------------------------------------------------------
// Kernel 3b: e1 = (Y1+Y2)^T @ w1^T + b1 via K=256 GEMM over g_Y,
// lrelu, sum over t -> atomicAdd into g_M. 4-stage cp.async ring.
// A[j][k] = w1[j][k & 127]  (weight repeated for the two Y halves)
// ----------------------------------------------------------------------------
__global__ __launch_bounds__(256) void emb1_mma_kernel(const float* __restrict__ w1,
                                                       const float* __restrict__ b1v)
{
    extern __shared__ __align__(16) float sm[];

    const int tid  = threadIdx.x;
    const int lane = tid & 31;
    const int wid  = tid >> 5;
    const int g    = lane >> 2;
    const int tig  = lane & 3;
    const int wm   = (wid & 1) * 64;
    const int wn   = (wid >> 1) * 32;

    const int n0 = blockIdx.x * 128;

    const int rowA = tid >> 1;
    const int kA   = (tid & 1) * 8;
    const int rowB = tid >> 4;
    const int nB   = (tid & 15) * 8;

    unsigned aAddr[4], bAddr[4];
#pragma unroll
    for (int st = 0; st < 4; st++) {
        aAddr[st] = sptr(sm + st * STG_FLOATS + rowA * ASTR + kA);
        bAddr[st] = sptr(sm + st * STG_FLOATS + BOFF + rowB * BSTR + nB);
    }

    float c[4][4][4];
#pragma unroll
    for (int i = 0; i < 4; i++)
#pragma unroll
        for (int j = 0; j < 4; j++)
#pragma unroll
            for (int k = 0; k < 4; k++) c[i][j][k] = 0.f;

    // prologue: stages 0..2
#pragma unroll
    for (int s = 0; s < 3; s++) {
        const float* wp = w1 + (size_t)rowA * DD + ((s * 16) & 127) + kA;
        cp16(aAddr[s], wp); cp16(aAddr[s] + 16, wp + 4);
        const float* yp = g_Y + (size_t)(s * 16 + rowB) * NTOT + n0 + nB;
        cp16(bAddr[s], yp); cp16(bAddr[s] + 16, yp + 4);
        CP_COMMIT();
    }

    const int NS = (2 * DD) / 16;   // 16 stages
    for (int s = 0; s < NS; s++) {
        CP_WAIT2();
        __syncthreads();

        if (s + 3 < NS) {
            const int d0 = (s + 3) * 16;
            const int b3 = (s + 3) & 3;
            const float* wp = w1 + (size_t)rowA * DD + (d0 & 127) + kA;
            cp16(aAddr[b3], wp); cp16(aAddr[b3] + 16, wp + 4);
            const float* yp = g_Y + (size_t)(d0 + rowB) * NTOT + n0 + nB;
            cp16(bAddr[b3], yp); cp16(bAddr[b3] + 16, yp + 4);
        }
        CP_COMMIT();

        const float* A = sm + (s & 3) * STG_FLOATS;
        const float* B = A + BOFF;
#pragma unroll
        for (int kh = 0; kh < 16; kh += 8) {
            unsigned a[4][4], b[4][2];
#pragma unroll
            for (int mt = 0; mt < 4; mt++) {
                const int m = wm + mt * 16 + g;
                a[mt][0] = __float_as_uint(A[m * ASTR + kh + tig]);
                a[mt][1] = __float_as_uint(A[(m + 8) * ASTR + kh + tig]);
                a[mt][2] = __float_as_uint(A[m * ASTR + kh + tig + 4]);
                a[mt][3] = __float_as_uint(A[(m + 8) * ASTR + kh + tig + 4]);
            }
#pragma unroll
            for (int nt = 0; nt < 4; nt++) {
                const int n = wn + nt * 8 + g;
                b[nt][0] = __float_as_uint(B[(kh + tig) * BSTR + n]);
                b[nt][1] = __float_as_uint(B[(kh + tig + 4) * BSTR + n]);
            }
#pragma unroll
            for (int mt = 0; mt < 4; mt++)
#pragma unroll
                for (int nt = 0; nt < 4; nt++)
                    mma_tf32(c[mt][nt], a[mt], b[nt]);
        }
    }

    // epilogue: bias + leaky-relu + sum over n, quad-reduce, atomicAdd
    const int bb = blockIdx.x >> 2;   // 4 n-tiles (of 128) per batch
#pragma unroll
    for (int mt = 0; mt < 4; mt++) {
        const int jr = wm + mt * 16 + g;
        const float bv0 = b1v[jr];
        const float bv1 = b1v[jr + 8];
        float r0 = 0.f, r1 = 0.f;
#pragma unroll
        for (int nt = 0; nt < 4; nt++) {
            float e;
            e = c[mt][nt][0] + bv0; r0 += (e >= 0.f) ? e : 0.2f * e;
            e = c[mt][nt][1] + bv0; r0 += (e >= 0.f) ? e : 0.2f * e;
            e = c[mt][nt][2] + bv1; r1 += (e >= 0.f) ? e : 0.2f * e;
            e = c[mt][nt][3] + bv1; r1 += (e >= 0.f) ? e : 0.2f * e;
        }
        r0 += __shfl_xor_sync(0xffffffffu, r0, 1);
        r0 += __shfl_xor_sync(0xffffffffu, r0, 2);
        r1 += __shfl_xor_sync(0xffffffffu, r1, 1);
        r1 += __shfl_xor_sync(0xffffffffu, r1, 2);
        if (tig == 0) {
            atomicAdd(&g_M[bb * DD + jr], r0);
            atomicAdd(&g_M[bb * DD + jr + 8], r1);
        }
    }
}

// ----------------------------------------------------------------------------
// Kernel 4: out[b][i] = (1/T) * sum_j g_M[b][j] * emb_w2[i][j] + emb_b2[i]
// ----------------------------------------------------------------------------
__global__ __launch_bounds__(128) void out_kernel(const float* __restrict__ w2,
                                                  const float* __restrict__ b2,
                                                  float* __restrict__ out)
{
    __shared__ float m[128];
    const int b = blockIdx.x;
    const int i = threadIdx.x;
    m[i] = g_M[b * DD + i] * (1.f / (float)TT);
    __syncthreads();
    float s = b2[i];
    const float* wr = w2 + i * DD;
#pragma unroll 16
    for (int j = 0; j < DD; j++) s = fmaf(m[j], wr[j], s);
    out[b * DD + i] = s;
}

// ----------------------------------------------------------------------------
extern "C" void kernel_launch(void* const* d_in, const int* in_sizes, int n_in,
                              void* d_out, int out_size)
{
    const float* x      = (const float*)d_in[0];
    const float* fc1_w  = (const float*)d_in[1];
    const float* fc1_b  = (const float*)d_in[2];
    const float* wih_f  = (const float*)d_in[3];
    const float* whh_f  = (const float*)d_in[4];
    const float* bih_f  = (const float*)d_in[5];
    const float* bhh_f  = (const float*)d_in[6];
    const float* wih_b  = (const float*)d_in[7];
    const float* whh_b  = (const float*)d_in[8];
    const float* bih_b  = (const float*)d_in[9];
    const float* bhh_b  = (const float*)d_in[10];
    const float* lout_w = (const float*)d_in[11];
    const float* lout_b = (const float*)d_in[12];
    const float* emb_w1 = (const float*)d_in[13];
    const float* emb_b1 = (const float*)d_in[14];
    const float* emb_w2 = (const float*)d_in[15];
    const float* emb_b2 = (const float*)d_in[16];
    float* out = (float*)d_out;

    static bool attr_done = false;
    if (!attr_done) {
        cudaFuncSetAttribute(fc1_mma_kernel,
                             cudaFuncAttributeMaxDynamicSharedMemorySize, SMEM_BYTES);
        cudaFuncSetAttribute(emb1_mma_kernel,
                             cudaFuncAttributeMaxDynamicSharedMemorySize, SMEM_BYTES);
        attr_done = true;
    }

    fc1_mma_kernel<<<dim3(TT / 128, BB), 256, SMEM_BYTES>>>(x, fc1_w, fc1_b);
    lstm_kernel<<<dim3(NTOT / 256, 2), 256>>>(wih_f, whh_f, bih_f, bhh_f,
                                              wih_b, whh_b, bih_b, bhh_b,
                                              lout_w, lout_b);
    zero_kernel<<<(BB * DD + 255) / 256, 256>>>();
    emb1_mma_kernel<<<NTOT / 128, 256, SMEM_BYTES>>>(emb_w1, emb_b1);
    out_kernel<<<BB, 128>>>(emb_w2, emb_b2, out);
}

// round 6
// speedup vs baseline: 2.8402x; 1.0070x over previous
#include <cuda_runtime.h>
#include <cstdint>

// Problem constants
#define BB   64
#define TT   512
#define NTOT 32768      // BB*TT
#define FF   1024
#define DD   128

// Scratch (device globals; no allocation allowed)
__device__ float g_G[DD * NTOT];       // fc1 output, layout [d][n]
__device__ float g_Y[2 * DD * NTOT];   // rows 0..127: lw0*h_fwd+lb ; 128..255: lw1*h_bwd
__device__ float g_M[BB * DD];         // sum over t of lrelu(e1)

// ---------------------------------------------------------------- helpers
__device__ __forceinline__ float mtanh(float x) {
    float y;
    asm("tanh.approx.f32 %0, %1;" : "=f"(y) : "f"(x));
    return y;
}
__device__ __forceinline__ unsigned sptr(const void* p) {
    return (unsigned)__cvta_generic_to_shared(p);
}
__device__ __forceinline__ void cp16(unsigned dst, const float* src) {
    asm volatile("cp.async.cg.shared.global [%0], [%1], 16;" :: "r"(dst), "l"(src));
}
#define CP_COMMIT() asm volatile("cp.async.commit_group;")
#define CP_WAIT1()  asm volatile("cp.async.wait_group 1;")

__device__ __forceinline__ void mma_tf32(float c[4], const unsigned a[4], const unsigned b[2]) {
    asm volatile(
        "mma.sync.aligned.m16n8k8.row.col.f32.tf32.tf32.f32 "
        "{%0,%1,%2,%3}, {%4,%5,%6,%7}, {%8,%9}, {%0,%1,%2,%3};"
        : "+f"(c[0]), "+f"(c[1]), "+f"(c[2]), "+f"(c[3])
        : "r"(a[0]), "r"(a[1]), "r"(a[2]), "r"(a[3]), "r"(b[0]), "r"(b[1]));
}

// GEMM tiling: CTA 128(M) x 256(N), 8 warps 2x4, warp tile 64x64, BK=16.
#define ASTR 20                       // A smem row stride (floats), [m][k]
#define BSTR 264                      // B smem row stride (floats), [k][n]
#define A_FL (128 * ASTR)             // 2560 floats
#define B_FL (16 * BSTR)              // 4224 floats
#define STG_FL (A_FL + B_FL)          // 6784 floats / stage
#define GSMEM_BYTES (3 * STG_FL * 4)  // 81408 bytes (3-stage ring)

// ----------------------------------------------------------------------------
// Shared GEMM mainloop body (as a macro-free inline pattern, duplicated per
// kernel to keep the epilogues simple).
// Fragment mapping per warp (m16n8k8):
//   wm = (wid&1)*64, wn = (wid>>1)*64
//   a[mt][0..3]: rows wm+mt*16+g, +8 ; k = kh+tig, kh+tig+4
//   b[nt][0..1]: col wn+nt*8+g     ; k = kh+tig, kh+tig+4
// ----------------------------------------------------------------------------

// ----------------------------------------------------------------------------
// Kernel 1: fc1 GEMM.  G[d][b*TT+t] = sum_f w[d][f]*x[b][f][t] + bias[d]
// ----------------------------------------------------------------------------
__global__ __launch_bounds__(256, 1) void fc1_mma_kernel(const float* __restrict__ x,
                                                         const float* __restrict__ w,
                                                         const float* __restrict__ bias)
{
    extern __shared__ __align__(16) float sm[];

    const int tid  = threadIdx.x;
    const int lane = tid & 31;
    const int wid  = tid >> 5;
    const int g    = lane >> 2;
    const int tig  = lane & 3;
    const int wm   = (wid & 1) * 64;
    const int wn   = (wid >> 1) * 64;

    const int bt = blockIdx.y;
    const int t0 = blockIdx.x * 256;
    const float* xb = x + (size_t)bt * FF * TT;

    // global->smem assignments
    const int rowA = tid >> 1;            // d row (0..127)
    const int kA   = (tid & 1) * 8;       // k offset: 2 cp16
    const int rowB = tid >> 4;            // k row (0..15)
    const int nB   = (tid & 15) * 16;     // t offset: 4 cp16

    unsigned aAddr[3], bAddr[3];
#pragma unroll
    for (int st = 0; st < 3; st++) {
        aAddr[st] = sptr(sm + st * STG_FL + rowA * ASTR + kA);
        bAddr[st] = sptr(sm + st * STG_FL + A_FL + rowB * BSTR + nB);
    }

    float c[4][8][4];
#pragma unroll
    for (int i = 0; i < 4; i++)
#pragma unroll
        for (int j = 0; j < 8; j++)
#pragma unroll
            for (int k = 0; k < 4; k++) c[i][j][k] = 0.f;

    // prologue: stages 0,1
#pragma unroll
    for (int s = 0; s < 2; s++) {
        const float* wp = w + (size_t)rowA * FF + s * 16 + kA;
        cp16(aAddr[s], wp); cp16(aAddr[s] + 16, wp + 4);
        const float* xp = xb + (size_t)(s * 16 + rowB) * TT + t0 + nB;
        cp16(bAddr[s], xp); cp16(bAddr[s] + 16, xp + 4);
        cp16(bAddr[s] + 32, xp + 8); cp16(bAddr[s] + 48, xp + 12);
        CP_COMMIT();
    }

    const int NS = FF / 16;   // 64 stages
    for (int s = 0; s < NS; s++) {
        CP_WAIT1();           // stage s landed
        __syncthreads();      // everyone done with buffer (s+2)%3

        if (s + 2 < NS) {
            const int f0 = (s + 2) * 16;
            const int b2 = (s + 2) % 3;
            const float* wp = w + (size_t)rowA * FF + f0 + kA;
            cp16(aAddr[b2], wp); cp16(aAddr[b2] + 16, wp + 4);
            const float* xp = xb + (size_t)(f0 + rowB) * TT + t0 + nB;
            cp16(bAddr[b2], xp); cp16(bAddr[b2] + 16, xp + 4);
            cp16(bAddr[b2] + 32, xp + 8); cp16(bAddr[b2] + 48, xp + 12);
        }
        CP_COMMIT();

        const float* A = sm + (s % 3) * STG_FL;
        const float* B = A + A_FL;
#pragma unroll
        for (int kh = 0; kh < 16; kh += 8) {
            unsigned a[4][4], b[8][2];
#pragma unroll
            for (int mt = 0; mt < 4; mt++) {
                const int m = wm + mt * 16 + g;
                a[mt][0] = __float_as_uint(A[m * ASTR + kh + tig]);
                a[mt][1] = __float_as_uint(A[(m + 8) * ASTR + kh + tig]);
                a[mt][2] = __float_as_uint(A[m * ASTR + kh + tig + 4]);
                a[mt][3] = __float_as_uint(A[(m + 8) * ASTR + kh + tig + 4]);
            }
#pragma unroll
            for (int nt = 0; nt < 8; nt++) {
                const int n = wn + nt * 8 + g;
                b[nt][0] = __float_as_uint(B[(kh + tig) * BSTR + n]);
                b[nt][1] = __float_as_uint(B[(kh + tig + 4) * BSTR + n]);
            }
#pragma unroll
            for (int mt = 0; mt < 4; mt++)
#pragma unroll
                for (int nt = 0; nt < 8; nt++)
                    mma_tf32(c[mt][nt], a[mt], b[nt]);
        }
    }

    // epilogue: add bias, store to g_G[d][n]
    const int nbase = bt * TT + t0 + wn;
#pragma unroll
    for (int mt = 0; mt < 4; mt++) {
        const int dr = wm + mt * 16 + g;
        const float bv0 = bias[dr];
        const float bv1 = bias[dr + 8];
#pragma unroll
        for (int nt = 0; nt < 8; nt++) {
            const int ncol = nbase + nt * 8 + 2 * tig;
            float2 v0 = make_float2(c[mt][nt][0] + bv0, c[mt][nt][1] + bv0);
            float2 v1 = make_float2(c[mt][nt][2] + bv1, c[mt][nt][3] + bv1);
            *reinterpret_cast<float2*>(g_G + (size_t)dr * NTOT + ncol) = v0;
            *reinterpret_cast<float2*>(g_G + (size_t)(dr + 8) * NTOT + ncol) = v1;
        }
    }
}

// ----------------------------------------------------------------------------
// Kernel 2: LSTM, one direction per blockIdx.y. H=1, MUFU.TANH path.
// ----------------------------------------------------------------------------
__global__ __launch_bounds__(256) void lstm_kernel(
    const float* __restrict__ wih_f, const float* __restrict__ whh_f,
    const float* __restrict__ bih_f, const float* __restrict__ bhh_f,
    const float* __restrict__ wih_b, const float* __restrict__ whh_b,
    const float* __restrict__ bih_b, const float* __restrict__ bhh_b,
    const float* __restrict__ lout_w, const float* __restrict__ lout_b)
{
    const int n = blockIdx.x * blockDim.x + threadIdx.x;
    const int dir = blockIdx.y;

    const float* wih = dir ? wih_b : wih_f;
    const float* whh = dir ? whh_b : whh_f;
    const float* bih = dir ? bih_b : bih_f;
    const float* bhh = dir ? bhh_b : bhh_f;

    const float wi0 = 0.5f * wih[0], wh0 = 0.5f * whh[0], b0 = 0.5f * (bih[0] + bhh[0]);
    const float wi1 = 0.5f * wih[1], wh1 = 0.5f * whh[1], b1 = 0.5f * (bih[1] + bhh[1]);
    const float wi2 =        wih[2], wh2 =        whh[2], b2 =        (bih[2] + bhh[2]);
    const float wi3 = 0.5f * wih[3], wh3 = 0.5f * whh[3], b3 = 0.5f * (bih[3] + bhh[3]);

    const float lw = dir ? lout_w[1] : lout_w[0];
    const float lb = dir ? 0.f : lout_b[0];

    float h = 0.f, c = 0.f;
    if (dir == 0) {
#pragma unroll 4
        for (int d = 0; d < DD; d++) {
            const float xv = g_G[(size_t)d * NTOT + n];
            const float si = fmaf(0.5f, mtanh(fmaf(wi0, xv, fmaf(wh0, h, b0))), 0.5f);
            const float sf = fmaf(0.5f, mtanh(fmaf(wi1, xv, fmaf(wh1, h, b1))), 0.5f);
            const float tg = mtanh(fmaf(wi2, xv, fmaf(wh2, h, b2)));
            const float so = fmaf(0.5f, mtanh(fmaf(wi3, xv, fmaf(wh3, h, b3))), 0.5f);
            c = fmaf(sf, c, si * tg);
            h = so * mtanh(c);
            g_Y[(size_t)d * NTOT + n] = fmaf(lw, h, lb);
        }
    } else {
#pragma unroll 4
        for (int d = DD - 1; d >= 0; d--) {
            const float xv = g_G[(size_t)d * NTOT + n];
            const float si = fmaf(0.5f, mtanh(fmaf(wi0, xv, fmaf(wh0, h, b0))), 0.5f);
            const float sf = fmaf(0.5f, mtanh(fmaf(wi1, xv, fmaf(wh1, h, b1))), 0.5f);
            const float tg = mtanh(fmaf(wi2, xv, fmaf(wh2, h, b2)));
            const float so = fmaf(0.5f, mtanh(fmaf(wi3, xv, fmaf(wh3, h, b3))), 0.5f);
            c = fmaf(sf, c, si * tg);
            h = so * mtanh(c);
            g_Y[(size_t)(DD + d) * NTOT + n] = lw * h;
        }
    }
}

// ----------------------------------------------------------------------------
// Kernel 3a: zero the mean accumulator.
// ----------------------------------------------------------------------------
__global__ void zero_kernel()
{
    const int i = blockIdx.x * blockDim.x + threadIdx.x;
    if (i < BB * DD) g_M[i] = 0.f;
}

// ----------------------------------------------------------------------------
// Kernel 3b: e1 = (Yf+Yb)^T @ w1^T + b1 via K=256 GEMM over g_Y,
// lrelu, sum over t -> atomicAdd into g_M. Same 128x256 tiling.
// A[j][k] = w1[j][k & 127] (weight repeated over the two Y halves).
// ----------------------------------------------------------------------------
__global__ __launch_bounds__(256, 1) void emb1_mma_kernel(const float* __restrict__ w1,
                                                          const float* __restrict__ b1v)
{
    extern __shared__ __align__(16) float sm[];

    const int tid  = threadIdx.x;
    const int lane = tid & 31;
    const int wid  = tid >> 5;
    const int g    = lane >> 2;
    const int tig  = lane & 3;
    const int wm   = (wid & 1) * 64;
    const int wn   = (wid >> 1) * 64;

    const int n0 = blockIdx.x * 256;

    const int rowA = tid >> 1;
    const int kA   = (tid & 1) * 8;
    const int rowB = tid >> 4;
    const int nB   = (tid & 15) * 16;

    unsigned aAddr[3], bAddr[3];
#pragma unroll
    for (int st = 0; st < 3; st++) {
        aAddr[st] = sptr(sm + st * STG_FL + rowA * ASTR + kA);
        bAddr[st] = sptr(sm + st * STG_FL + A_FL + rowB * BSTR + nB);
    }

    float c[4][8][4];
#pragma unroll
    for (int i = 0; i < 4; i++)
#pragma unroll
        for (int j = 0; j < 8; j++)
#pragma unroll
            for (int k = 0; k < 4; k++) c[i][j][k] = 0.f;

#pragma unroll
    for (int s = 0; s < 2; s++) {
        const float* wp = w1 + (size_t)rowA * DD + ((s * 16) & 127) + kA;
        cp16(aAddr[s], wp); cp16(aAddr[s] + 16, wp + 4);
        const float* yp = g_Y + (size_t)(s * 16 + rowB) * NTOT + n0 + nB;
        cp16(bAddr[s], yp); cp16(bAddr[s] + 16, yp + 4);
        cp16(bAddr[s] + 32, yp + 8); cp16(bAddr[s] + 48, yp + 12);
        CP_COMMIT();
    }

    const int NS = (2 * DD) / 16;   // 16 stages
    for (int s = 0; s < NS; s++) {
        CP_WAIT1();
        __syncthreads();

        if (s + 2 < NS) {
            const int d0 = (s + 2) * 16;
            const int b2 = (s + 2) % 3;
            const float* wp = w1 + (size_t)rowA * DD + (d0 & 127) + kA;
            cp16(aAddr[b2], wp); cp16(aAddr[b2] + 16, wp + 4);
            const float* yp = g_Y + (size_t)(d0 + rowB) * NTOT + n0 + nB;
            cp16(bAddr[b2], yp); cp16(bAddr[b2] + 16, yp + 4);
            cp16(bAddr[b2] + 32, yp + 8); cp16(bAddr[b2] + 48, yp + 12);
        }
        CP_COMMIT();

        const float* A = sm + (s % 3) * STG_FL;
        const float* B = A + A_FL;
#pragma unroll
        for (int kh = 0; kh < 16; kh += 8) {
            unsigned a[4][4], b[8][2];
#pragma unroll
            for (int mt = 0; mt < 4; mt++) {
                const int m = wm + mt * 16 + g;
                a[mt][0] = __float_as_uint(A[m * ASTR + kh + tig]);
                a[mt][1] = __float_as_uint(A[(m + 8) * ASTR + kh + tig]);
                a[mt][2] = __float_as_uint(A[m * ASTR + kh + tig + 4]);
                a[mt][3] = __float_as_uint(A[(m + 8) * ASTR + kh + tig + 4]);
            }
#pragma unroll
            for (int nt = 0; nt < 8; nt++) {
                const int n = wn + nt * 8 + g;
                b[nt][0] = __float_as_uint(B[(kh + tig) * BSTR + n]);
                b[nt][1] = __float_as_uint(B[(kh + tig + 4) * BSTR + n]);
            }
#pragma unroll
            for (int mt = 0; mt < 4; mt++)
#pragma unroll
                for (int nt = 0; nt < 8; nt++)
                    mma_tf32(c[mt][nt], a[mt], b[nt]);
        }
    }

    // epilogue: bias + leaky-relu + sum over n, quad-reduce, atomicAdd
    const int bb = blockIdx.x >> 1;   // 2 n-tiles (of 256) per batch
#pragma unroll
    for (int mt = 0; mt < 4; mt++) {
        const int jr = wm + mt * 16 + g;
        const float bv0 = b1v[jr];
        const float bv1 = b1v[jr + 8];
        float r0 = 0.f, r1 = 0.f;
#pragma unroll
        for (int nt = 0; nt < 8; nt++) {
            float e;
            e = c[mt][nt][0] + bv0; r0 += (e >= 0.f) ? e : 0.2f * e;
            e = c[mt][nt][1] + bv0; r0 += (e >= 0.f) ? e : 0.2f * e;
            e = c[mt][nt][2] + bv1; r1 += (e >= 0.f) ? e : 0.2f * e;
            e = c[mt][nt][3] + bv1; r1 += (e >= 0.f) ? e : 0.2f * e;
        }
        r0 += __shfl_xor_sync(0xffffffffu, r0, 1);
        r0 += __shfl_xor_sync(0xffffffffu, r0, 2);
        r1 += __shfl_xor_sync(0xffffffffu, r1, 1);
        r1 += __shfl_xor_sync(0xffffffffu, r1, 2);
        if (tig == 0) {
            atomicAdd(&g_M[bb * DD + jr], r0);
            atomicAdd(&g_M[bb * DD + jr + 8], r1);
        }
    }
}

// ----------------------------------------------------------------------------
// Kernel 4: out[b][i] = (1/T) * sum_j g_M[b][j] * emb_w2[i][j] + emb_b2[i]
// ----------------------------------------------------------------------------
__global__ __launch_bounds__(128) void out_kernel(const float* __restrict__ w2,
                                                  const float* __restrict__ b2,
                                                  float* __restrict__ out)
{
    __shared__ float m[128];
    const int b = blockIdx.x;
    const int i = threadIdx.x;
    m[i] = g_M[b * DD + i] * (1.f / (float)TT);
    __syncthreads();
    float s = b2[i];
    const float* wr = w2 + i * DD;
#pragma unroll 16
    for (int j = 0; j < DD; j++) s = fmaf(m[j], wr[j], s);
    out[b * DD + i] = s;
}

// ----------------------------------------------------------------------------
extern "C" void kernel_launch(void* const* d_in, const int* in_sizes, int n_in,
                              void* d_out, int out_size)
{
    const float* x      = (const float*)d_in[0];
    const float* fc1_w  = (const float*)d_in[1];
    const float* fc1_b  = (const float*)d_in[2];
    const float* wih_f  = (const float*)d_in[3];
    const float* whh_f  = (const float*)d_in[4];
    const float* bih_f  = (const float*)d_in[5];
    const float* bhh_f  = (const float*)d_in[6];
    const float* wih_b  = (const float*)d_in[7];
    const float* whh_b  = (const float*)d_in[8];
    const float* bih_b  = (const float*)d_in[9];
    const float* bhh_b  = (const float*)d_in[10];
    const float* lout_w = (const float*)d_in[11];
    const float* lout_b = (const float*)d_in[12];
    const float* emb_w1 = (const float*)d_in[13];
    const float* emb_b1 = (const float*)d_in[14];
    const float* emb_w2 = (const float*)d_in[15];
    const float* emb_b2 = (const float*)d_in[16];
    float* out = (float*)d_out;

    cudaFuncSetAttribute(fc1_mma_kernel,
                         cudaFuncAttributeMaxDynamicSharedMemorySize, GSMEM_BYTES);
    cudaFuncSetAttribute(emb1_mma_kernel,
                         cudaFuncAttributeMaxDynamicSharedMemorySize, GSMEM_BYTES);

    fc1_mma_kernel<<<dim3(TT / 256, BB), 256, GSMEM_BYTES>>>(x, fc1_w, fc1_b);
    lstm_kernel<<<dim3(NTOT / 256, 2), 256>>>(wih_f, whh_f, bih_f, bhh_f,
                                              wih_b, whh_b, bih_b, bhh_b,
                                              lout_w, lout_b);
    zero_kernel<<<(BB * DD + 255) / 256, 256>>>();
    emb1_mma_kernel<<<NTOT / 256, 256, GSMEM_BYTES>>>(emb_w1, emb_b1);
    out_kernel<<<BB, 128>>>(emb_w2, emb_b2, out);
}